// round 14
// baseline (speedup 1.0000x reference)
#include <cuda_runtime.h>
#include <cuda_fp16.h>
#include <math.h>
#include <stdint.h>

#define BB   4
#define CC   256
#define CSd  128
#define NN   4096
#define EPSc 1e-5f
#define LOG2E 1.4426950408889634f

typedef unsigned long long ull;
typedef unsigned int u32;

// ---------------- misc helpers ----------------
__device__ __forceinline__ u32 cvt_bf2(float v1, float v0){
    u32 r; asm("cvt.rn.bf16x2.f32 %0, %1, %2;" : "=r"(r) : "f"(v1), "f"(v0)); return r;
}
__device__ __forceinline__ float ex2f(float x){
    float r; asm("ex2.approx.f32 %0, %1;" : "=f"(r) : "f"(x)); return r;
}
__device__ __forceinline__ u32 smem_u32(const void* p){
    u32 a; asm("{ .reg .u64 t; cvta.to.shared.u64 t, %1; cvt.u32.u64 %0, t; }" : "=r"(a) : "l"(p));
    return a;
}
__device__ __forceinline__ u32 packf16(float v1, float v0){
    __half2 t = __floats2half2_rn(v0, v1);
    return *(u32*)&t;
}
__device__ __forceinline__ void splitf16(float v1, float v0, u32& h, u32& l){
    __half a0 = __float2half_rn(v0), a1 = __float2half_rn(v1);
    __half2 hh = __halves2half2(a0, a1);
    h = *(u32*)&hh;
    __half2 ll = __floats2half2_rn(v0 - __half2float(a0), v1 - __half2float(a1));
    l = *(u32*)&ll;
}

// ---------------- warp-MMA + cp.async helpers ------------------------------
__device__ __forceinline__ void ldsm_x4(u32& r0,u32& r1,u32& r2,u32& r3, u32 addr){
    asm volatile("ldmatrix.sync.aligned.m8n8.x4.shared.b16 {%0,%1,%2,%3}, [%4];"
        : "=r"(r0),"=r"(r1),"=r"(r2),"=r"(r3) : "r"(addr));
}
__device__ __forceinline__ void ldsm_x4_t(u32& r0,u32& r1,u32& r2,u32& r3, u32 addr){
    asm volatile("ldmatrix.sync.aligned.m8n8.x4.trans.shared.b16 {%0,%1,%2,%3}, [%4];"
        : "=r"(r0),"=r"(r1),"=r"(r2),"=r"(r3) : "r"(addr));
}
__device__ __forceinline__ void mma_bf16(float* d, const u32* a, const u32* b){
    asm volatile("mma.sync.aligned.m16n8k16.row.col.f32.bf16.bf16.f32 "
        "{%0,%1,%2,%3}, {%4,%5,%6,%7}, {%8,%9}, {%0,%1,%2,%3};"
        : "+f"(d[0]),"+f"(d[1]),"+f"(d[2]),"+f"(d[3])
        : "r"(a[0]),"r"(a[1]),"r"(a[2]),"r"(a[3]), "r"(b[0]),"r"(b[1]));
}
__device__ __forceinline__ void mma_f16(float* d, const u32* a, const u32* b){
    asm volatile("mma.sync.aligned.m16n8k16.row.col.f32.f16.f16.f32 "
        "{%0,%1,%2,%3}, {%4,%5,%6,%7}, {%8,%9}, {%0,%1,%2,%3};"
        : "+f"(d[0]),"+f"(d[1]),"+f"(d[2]),"+f"(d[3])
        : "r"(a[0]),"r"(a[1]),"r"(a[2]),"r"(a[3]), "r"(b[0]),"r"(b[1]));
}
#define CP16(dst, src)  asm volatile("cp.async.cg.shared.global [%0], [%1], 16;" :: "r"(dst), "l"(src))
#define CP_COMMIT()     asm volatile("cp.async.commit_group;" ::: "memory")
#define CP_WAIT1()      asm volatile("cp.async.wait_group 1;" ::: "memory")
#define CP_WAIT0()      asm volatile("cp.async.wait_group 0;" ::: "memory")

// ---------------- scratch (device globals; no allocations) ----------------
__device__ __align__(16) u32 d_Qh[BB*NN*64];   // fp16 [b][n][cs] pairs
__device__ __align__(16) u32 d_Ql[BB*NN*64];
__device__ __align__(16) u32 d_Kh[BB*NN*64];   // fp16 single
__device__ __align__(16) u32 d_Vh[BB*NN*64];   // fp16 single
__device__ __align__(16) u32 d_Oh[BB*NN*64];   // bf16 splits (oproj input)
__device__ __align__(16) u32 d_Ol[BB*NN*64];
__device__ __align__(16) u32 d_xh[BB*NN*128];  // bf16 splits
__device__ __align__(16) u32 d_xl[BB*NN*128];
__device__ __align__(16) u32 d_Wh[3*CSd*128];
__device__ __align__(16) u32 d_Wl[3*CSd*128];
__device__ __align__(16) u32 d_Woh[CC*64];
__device__ __align__(16) u32 d_Wol[CC*64];
__device__ float d_Y[BB*CC*NN];
__device__ float d_ps1[128*CC];
__device__ float d_ps2[128*CC];
__device__ float d_scale[CC];
__device__ float d_shift[CC];

// ======================= Prep 1: weight splits (bf16) =======================
__global__ __launch_bounds__(256) void wsplit_kernel(
    const float* __restrict__ Wq, const float* __restrict__ Wk,
    const float* __restrict__ Wv, const float* __restrict__ Wo)
{
    const int z = blockIdx.y;
    #pragma unroll
    for (int it = 0; it < 8; it++) {
        int i = blockIdx.x*2048 + threadIdx.x + it*256;
        float v0, v1;
        if (z < 3) {
            const float* W = (z==0) ? Wq : (z==1) ? Wk : Wv;
            int cs = i >> 7, jp = i & 127;
            v0 = W[cs*CC + 2*jp]; v1 = W[cs*CC + 2*jp + 1];
        } else {
            int c = i >> 6, jp = i & 63;
            v0 = Wo[c*CSd + 2*jp]; v1 = Wo[c*CSd + 2*jp + 1];
        }
        u32 h = cvt_bf2(v1, v0);
        float f1 = __uint_as_float(h & 0xffff0000u);
        float f0 = __uint_as_float(h << 16);
        u32 l = cvt_bf2(v1 - f1, v0 - f0);
        if (z < 3) { d_Wh[z*16384 + i] = h; d_Wl[z*16384 + i] = l; }
        else       { d_Woh[i] = h;          d_Wol[i] = l; }
    }
}

// ======================= Prep 2: x transpose + split (bf16) =================
__global__ __launch_bounds__(256) void xsplit_kernel(const float* __restrict__ x)
{
    __shared__ float t[64*65];
    const int b  = blockIdx.z;
    const int c0 = blockIdx.y * 64;
    const int n0 = blockIdx.x * 64;
    const int tid = threadIdx.x;
    #pragma unroll
    for (int it = 0; it < 16; it++) {
        int idx = tid + it*256;
        int r = idx >> 6, col = idx & 63;
        t[r*65 + col] = x[(size_t)(b*CC + c0 + r)*NN + n0 + col];
    }
    __syncthreads();
    #pragma unroll
    for (int it = 0; it < 8; it++) {
        int idx = tid + it*256;
        int nl = idx >> 5, jp = idx & 31;
        float v0 = t[(2*jp)*65 + nl], v1 = t[(2*jp+1)*65 + nl];
        u32 h = cvt_bf2(v1, v0);
        float f1 = __uint_as_float(h & 0xffff0000u);
        float f0 = __uint_as_float(h << 16);
        size_t u = (size_t)(b*NN + n0 + nl)*128 + (c0 >> 1) + jp;
        d_xh[u] = h;
        d_xl[u] = cvt_bf2(v1 - f1, v0 - f0);
    }
}

// ======================= Kernel A: QKV projections (bf16 HMMA) ==============
// x tiles (both ch chunks) prefetched via cp.async; W loaded synchronously.
#define STB 272
#define TILE_B 34816
#define QOFF_W  (4*TILE_B)
#define QKV_SMEM (6*TILE_B)

__global__ __launch_bounds__(256, 1) void qkv_kernel(
    const float* __restrict__ bq, const float* __restrict__ bk,
    const float* __restrict__ bv)
{
    extern __shared__ __align__(16) char smem[];
    const u32 sb = smem_u32(smem);
    const int z  = blockIdx.z;
    const int b  = blockIdx.y;
    const int n0 = blockIdx.x * 128;
    const float* bias = (z==0) ? bq : (z==1) ? bk : bv;
    const float qsc = (z==0) ? LOG2E : 1.0f;
    const int tid = threadIdx.x;
    const int w = tid >> 5, lane = tid & 31;
    const int g = lane >> 3, lr = lane & 7, quad = lane & 3;

    // prefetch x(ch0) and x(ch1): tiles [2*ch + split]
    #pragma unroll
    for (int ch = 0; ch < 2; ch++) {
        #pragma unroll
        for (int i = 0; i < 16; i++) {
            int f = tid + i*256;            // 0..4095 uint4
            int sp = f >> 11, idx = f & 2047;
            int row = idx >> 4, c16 = idx & 15;
            const u32* src = (sp ? d_xl : d_xh)
                           + (size_t)(b*NN + n0 + row)*128 + ch*64 + c16*4;
            CP16(sb + (u32)((2*ch + sp)*TILE_B + row*STB + c16*16), src);
        }
        CP_COMMIT();
    }

    const u32 aB = sb + QOFF_W + (u32)(((g>>1)*8 + lr)*STB + (g&1)*16);

    float acc[16][4];
    #pragma unroll
    for (int nb = 0; nb < 16; nb++)
        #pragma unroll
        for (int e = 0; e < 4; e++) acc[nb][e] = 0.f;

    #pragma unroll
    for (int ch = 0; ch < 2; ch++) {
        // load W(z,ch) into WH/WL (regular stores)
        #pragma unroll
        for (int i = 0; i < 16; i++) {
            int f = tid + i*256;            // 0..4095 uint4
            int sp = f >> 11, idx = f & 2047;
            int row = idx >> 4, c16 = idx & 15;
            const u32* src = (sp ? d_Wl : d_Wh)
                           + (size_t)(z*CSd + row)*128 + ch*64 + c16*4;
            *(uint4*)(smem + QOFF_W + sp*TILE_B + row*STB + c16*16) = *(const uint4*)src;
        }
        if (ch == 0) CP_WAIT1(); else CP_WAIT0();
        __syncthreads();

        const u32 aA = sb + 2*ch*TILE_B + (u32)((w*16 + (g&1)*8 + lr)*STB + (g>>1)*16);
        #pragma unroll
        for (int ks = 0; ks < 8; ks++) {
            u32 ah[4], al[4];
            ldsm_x4(ah[0],ah[1],ah[2],ah[3], aA + ks*32);
            ldsm_x4(al[0],al[1],al[2],al[3], aA + TILE_B + ks*32);
            #pragma unroll
            for (int nbp = 0; nbp < 8; nbp++) {
                u32 bh[4], blo[4];
                ldsm_x4(bh[0],bh[1],bh[2],bh[3],     aB + nbp*16*STB + ks*32);
                ldsm_x4(blo[0],blo[1],blo[2],blo[3], aB + TILE_B + nbp*16*STB + ks*32);
                mma_bf16(acc[2*nbp],   ah, &bh[0]);
                mma_bf16(acc[2*nbp],   ah, &blo[0]);
                mma_bf16(acc[2*nbp],   al, &bh[0]);
                mma_bf16(acc[2*nbp+1], ah, &bh[2]);
                mma_bf16(acc[2*nbp+1], ah, &blo[2]);
                mma_bf16(acc[2*nbp+1], al, &bh[2]);
            }
        }
        __syncthreads();   // W reads done before ch1 overwrites
    }

    int r0 = n0 + w*16 + (lane >> 2);
    #pragma unroll
    for (int nb = 0; nb < 16; nb++) {
        int col = nb*8 + quad*2;
        float b0 = __ldg(&bias[col]), b1 = __ldg(&bias[col+1]);
        #pragma unroll
        for (int half = 0; half < 2; half++) {
            float v0 = (acc[nb][2*half]   + b0) * qsc;
            float v1 = (acc[nb][2*half+1] + b1) * qsc;
            size_t u = (size_t)(b*NN + r0 + half*8)*64 + nb*4 + quad;
            if (z == 0) {
                u32 h, l;
                splitf16(v1, v0, h, l);
                d_Qh[u] = h; d_Ql[u] = l;
            } else if (z == 1) {
                d_Kh[u] = packf16(v1, v0);
            } else {
                d_Vh[u] = packf16(v1, v0);
            }
        }
    }
}

// ======================= Kernel B: fp16 HMMA flash attention ================
// Qh Ql + double-buffered K, V (single fp16) = 6 x 34816 = 208896 B
#define OFF_QH 0
#define OFF_QL (1*TILE_B)
#define OFF_K0 (2*TILE_B)
#define OFF_K1 (3*TILE_B)
#define OFF_V0 (4*TILE_B)
#define OFF_V1 (5*TILE_B)
#define ATTN_SMEM_BYTES (6*TILE_B)

__device__ __forceinline__ void issue_t(u32 sb, int tid, int b, int kb,
                                        int off, const u32* src0)
{
    #pragma unroll
    for (int i = 0; i < 8; i++) {
        int f = tid + i*256;               // 0..2047 uint4
        int row = f >> 4, c16 = f & 15;
        const u32* src = src0 + (size_t)(b*NN + kb + row)*64 + c16*4;
        CP16(sb + (u32)(off + row*STB + c16*16), src);
    }
}

__global__ __launch_bounds__(256, 1) void attn_kernel()
{
    extern __shared__ __align__(16) char smem[];
    const u32 sb = smem_u32(smem);
    const int b  = blockIdx.y;
    const int q0 = blockIdx.x * 128;
    const int tid = threadIdx.x;
    const int w = tid >> 5, lane = tid & 31;
    const int g = lane >> 3, lr = lane & 7, quad = lane & 3;

    // Q tile fill (fp16 splits)
    #pragma unroll
    for (int i = 0; i < 16; i++) {
        int f = tid + i*256;
        int sp = f >> 11, idx = f & 2047;
        int row = idx >> 4, c16 = idx & 15;
        const u32* src = (sp ? d_Ql : d_Qh) + (size_t)(b*NN + q0 + row)*64 + c16*4;
        *(uint4*)(smem + (sp ? OFF_QL : OFF_QH) + row*STB + c16*16) = *(const uint4*)src;
    }

    const u32 aQh = sb + OFF_QH + (u32)((w*16 + (g&1)*8 + lr)*STB + (g>>1)*16);
    const u32 aQl = aQh + TILE_B;
    const u32 kOffs = (u32)(((g>>1)*8 + lr)*STB + (g&1)*16);
    const u32 vOffs = (u32)(((g&1)*8 + lr)*STB + (g>>1)*16);
    const u32 aKb[2] = { sb + OFF_K0 + kOffs, sb + OFF_K1 + kOffs };
    const u32 aVb[2] = { sb + OFF_V0 + vOffs, sb + OFF_V1 + vOffs };

    float o[16][4];
    #pragma unroll
    for (int nb = 0; nb < 16; nb++)
        #pragma unroll
        for (int e = 0; e < 4; e++) o[nb][e] = 0.f;
    float m0 = -1e30f, m1 = -1e30f, l0 = 0.f, l1 = 0.f;

    issue_t(sb, tid, b, 0, OFF_K0, d_Kh); CP_COMMIT();
    issue_t(sb, tid, b, 0, OFF_V0, d_Vh); CP_COMMIT();

    for (int kt = 0; kt < NN/128; kt++) {
        const int p = kt & 1;
        CP_WAIT1();                 // K(kt) ready (V(kt) may be in flight)
        __syncthreads();
        // prefetch K(kt+1) into alternate buffer (overlaps S+softmax+PV)
        if (kt + 1 < NN/128)
            issue_t(sb, tid, b, (kt+1)*128, p ? OFF_K0 : OFF_K1, d_Kh);
        CP_COMMIT();

        // ---- S = Q.K^T (fp16 2-split: Qh.K + Ql.K) ----
        const u32 aK = aKb[p];
        float s[16][4];
        #pragma unroll
        for (int nb = 0; nb < 16; nb++)
            #pragma unroll
            for (int e = 0; e < 4; e++) s[nb][e] = 0.f;
        #pragma unroll
        for (int ks = 0; ks < 8; ks++) {
            u32 ah[4], al[4];
            ldsm_x4(ah[0],ah[1],ah[2],ah[3], aQh + ks*32);
            ldsm_x4(al[0],al[1],al[2],al[3], aQl + ks*32);
            #pragma unroll
            for (int nbp = 0; nbp < 8; nbp++) {
                u32 kh[4];
                ldsm_x4(kh[0],kh[1],kh[2],kh[3], aK + nbp*16*STB + ks*32);
                mma_f16(s[2*nbp],   ah, &kh[0]);
                mma_f16(s[2*nbp],   al, &kh[0]);
                mma_f16(s[2*nbp+1], ah, &kh[2]);
                mma_f16(s[2*nbp+1], al, &kh[2]);
            }
        }

        // ---- row max + accumulator rescale ----
        float tm0 = -1e30f, tm1 = -1e30f;
        #pragma unroll
        for (int nb = 0; nb < 16; nb++) {
            tm0 = fmaxf(tm0, fmaxf(s[nb][0], s[nb][1]));
            tm1 = fmaxf(tm1, fmaxf(s[nb][2], s[nb][3]));
        }
        tm0 = fmaxf(tm0, __shfl_xor_sync(0xffffffffu, tm0, 1));
        tm0 = fmaxf(tm0, __shfl_xor_sync(0xffffffffu, tm0, 2));
        tm1 = fmaxf(tm1, __shfl_xor_sync(0xffffffffu, tm1, 1));
        tm1 = fmaxf(tm1, __shfl_xor_sync(0xffffffffu, tm1, 2));
        float nm0 = fmaxf(m0, tm0), nm1 = fmaxf(m1, tm1);
        float rs0 = ex2f(m0 - nm0), rs1 = ex2f(m1 - nm1);
        m0 = nm0; m1 = nm1;
        #pragma unroll
        for (int nb = 0; nb < 16; nb++) {
            o[nb][0] *= rs0; o[nb][1] *= rs0;
            o[nb][2] *= rs1; o[nb][3] *= rs1;
        }

        CP_WAIT1();                 // V(kt) ready (K(kt+1) in flight)
        __syncthreads();
        // prefetch V(kt+1) into alternate buffer
        if (kt + 1 < NN/128)
            issue_t(sb, tid, b, (kt+1)*128, p ? OFF_V0 : OFF_V1, d_Vh);
        CP_COMMIT();

        // ---- fused exp + fp16 pack + PV (single split) ----
        const u32 aV = aVb[p];
        float ps0 = 0.f, ps1 = 0.f;
        #pragma unroll
        for (int ks2 = 0; ks2 < 8; ks2++) {
            int na = 2*ks2, nbb = 2*ks2 + 1;
            float e00 = ex2f(s[na][0]  - nm0), e01 = ex2f(s[na][1]  - nm0);
            float e02 = ex2f(s[na][2]  - nm1), e03 = ex2f(s[na][3]  - nm1);
            float e10 = ex2f(s[nbb][0] - nm0), e11 = ex2f(s[nbb][1] - nm0);
            float e12 = ex2f(s[nbb][2] - nm1), e13 = ex2f(s[nbb][3] - nm1);
            ps0 += e00 + e01 + e10 + e11;
            ps1 += e02 + e03 + e12 + e13;
            u32 pah[4];
            pah[0] = packf16(e01, e00);
            pah[1] = packf16(e03, e02);
            pah[2] = packf16(e11, e10);
            pah[3] = packf16(e13, e12);
            #pragma unroll
            for (int nbp = 0; nbp < 8; nbp++) {
                u32 vh[4];
                ldsm_x4_t(vh[0],vh[1],vh[2],vh[3], aV + ks2*16*STB + nbp*32);
                mma_f16(o[2*nbp],   pah, &vh[0]);
                mma_f16(o[2*nbp+1], pah, &vh[2]);
            }
        }
        ps0 += __shfl_xor_sync(0xffffffffu, ps0, 1);
        ps0 += __shfl_xor_sync(0xffffffffu, ps0, 2);
        ps1 += __shfl_xor_sync(0xffffffffu, ps1, 1);
        ps1 += __shfl_xor_sync(0xffffffffu, ps1, 2);
        l0 = l0*rs0 + ps0;
        l1 = l1*rs1 + ps1;
    }

    // ---- epilogue: normalize, bf16 hi/lo split, write d_Oh/d_Ol ----
    float inv0 = 1.0f / l0, inv1 = 1.0f / l1;
    int r0g = q0 + w*16 + (lane >> 2);
    #pragma unroll
    for (int nb = 0; nb < 16; nb++) {
        #pragma unroll
        for (int half = 0; half < 2; half++) {
            float v0 = o[nb][2*half]   * (half ? inv1 : inv0);
            float v1 = o[nb][2*half+1] * (half ? inv1 : inv0);
            u32 h = cvt_bf2(v1, v0);
            float f1 = __uint_as_float(h & 0xffff0000u);
            float f0 = __uint_as_float(h << 16);
            size_t u = (size_t)(b*NN + r0g + half*8)*64 + nb*4 + quad;
            d_Oh[u] = h;
            d_Ol[u] = cvt_bf2(v1 - f1, v0 - f0);
        }
    }
}

// ======================= Kernel C: output projection (bf16 HMMA) ============
#define OPROJ_SMEM (4*TILE_B + 128*132*4)

__global__ __launch_bounds__(256, 1) void oproj_kernel(const float* __restrict__ bo)
{
    extern __shared__ __align__(16) char smem[];
    const u32 sb = smem_u32(smem);
    const int b  = blockIdx.z;
    const int c0 = blockIdx.y * 128;
    const int n0 = blockIdx.x * 128;
    const int tid = threadIdx.x;
    const int w = tid >> 5, lane = tid & 31;
    const int g = lane >> 3, lr = lane & 7, quad = lane & 3;

    #pragma unroll
    for (int i = 0; i < 32; i++) {
        int f = tid + i*256;
        int t4 = f >> 11, idx = f & 2047;
        int row = idx >> 4, c16 = idx & 15;
        const u32* src;
        if (t4 < 2)
            src = (t4 ? d_Ol : d_Oh) + (size_t)(b*NN + n0 + row)*64 + c16*4;
        else
            src = ((t4==2) ? d_Woh : d_Wol) + (size_t)(c0 + row)*64 + c16*4;
        *(uint4*)(smem + t4*TILE_B + row*STB + c16*16) = *(const uint4*)src;
    }
    __syncthreads();

    const u32 aA = sb + (u32)((w*16 + (g&1)*8 + lr)*STB + (g>>1)*16);
    const u32 aB = sb + 2*TILE_B + (u32)(((g>>1)*8 + lr)*STB + (g&1)*16);

    float acc[16][4];
    #pragma unroll
    for (int nb = 0; nb < 16; nb++)
        #pragma unroll
        for (int e = 0; e < 4; e++) acc[nb][e] = 0.f;

    #pragma unroll
    for (int ks = 0; ks < 8; ks++) {
        u32 ah[4], al[4];
        ldsm_x4(ah[0],ah[1],ah[2],ah[3], aA + ks*32);
        ldsm_x4(al[0],al[1],al[2],al[3], aA + TILE_B + ks*32);
        #pragma unroll
        for (int nbp = 0; nbp < 8; nbp++) {
            u32 bh[4], blo[4];
            ldsm_x4(bh[0],bh[1],bh[2],bh[3],     aB + nbp*16*STB + ks*32);
            ldsm_x4(blo[0],blo[1],blo[2],blo[3], aB + TILE_B + nbp*16*STB + ks*32);
            mma_bf16(acc[2*nbp],   ah, &bh[0]);
            mma_bf16(acc[2*nbp],   ah, &blo[0]);
            mma_bf16(acc[2*nbp],   al, &bh[0]);
            mma_bf16(acc[2*nbp+1], ah, &bh[2]);
            mma_bf16(acc[2*nbp+1], ah, &blo[2]);
            mma_bf16(acc[2*nbp+1], al, &bh[2]);
        }
    }
    __syncthreads();

    float* ys = (float*)(smem + 4*TILE_B);
    int r0 = w*16 + (lane >> 2);
    #pragma unroll
    for (int nb = 0; nb < 16; nb++) {
        int col = nb*8 + quad*2;
        float b0 = __ldg(&bo[c0+col]), b1 = __ldg(&bo[c0+col+1]);
        ys[col*132 + r0]         = acc[nb][0] + b0;
        ys[(col+1)*132 + r0]     = acc[nb][1] + b1;
        ys[col*132 + r0 + 8]     = acc[nb][2] + b0;
        ys[(col+1)*132 + r0 + 8] = acc[nb][3] + b1;
    }
    __syncthreads();

    {
        int c = tid >> 1, hn = (tid & 1) * 64;
        float s = 0.f, s2 = 0.f;
        #pragma unroll 8
        for (int j = 0; j < 64; j++) {
            float v = ys[c*132 + hn + j];
            s += v; s2 += v*v;
        }
        s  += __shfl_xor_sync(0xffffffffu, s, 1);
        s2 += __shfl_xor_sync(0xffffffffu, s2, 1);
        if (!(tid & 1)) {
            int j = b*32 + blockIdx.x;
            d_ps1[(size_t)j*CC + c0 + c] = s;
            d_ps2[(size_t)j*CC + c0 + c] = s2;
        }
    }

    #pragma unroll
    for (int i = 0; i < 16; i++) {
        int f = tid + i*256;
        int row = f >> 5, q4 = f & 31;
        *(float4*)&d_Y[(size_t)(b*CC + c0 + row)*NN + n0 + q4*4] =
            *(float4*)&ys[row*132 + q4*4];
    }
}

// ======================= Kernel D: BN stats from partials ===================
__global__ __launch_bounds__(256) void bnstat_kernel(
    const float* __restrict__ gamma, const float* __restrict__ beta)
{
    const int c = threadIdx.x;
    float s = 0.f, s2 = 0.f;
    #pragma unroll 8
    for (int j = 0; j < 128; j++) {
        s  += d_ps1[(size_t)j*CC + c];
        s2 += d_ps2[(size_t)j*CC + c];
    }
    float mean = s  * (1.f/16384.f);
    float var  = s2 * (1.f/16384.f) - mean*mean;
    float sc = gamma[c] * rsqrtf(var + EPSc);
    d_scale[c] = sc;
    d_shift[c] = beta[c] - mean*sc;
}

// ======================= Kernel E: BN affine + ReLU + residual ==============
__global__ __launch_bounds__(256) void epilogue_kernel(
    const float* __restrict__ x, float* __restrict__ out)
{
    int i4 = blockIdx.x*256 + threadIdx.x;
    int idx = i4 * 4;
    int c = (idx >> 12) & 255;
    float sc = d_scale[c], sh = d_shift[c];
    float4 y   = *(const float4*)&d_Y[idx];
    float4 xin = ((const float4*)x)[i4];
    float4 r;
    r.x = fmaxf(fmaf(y.x, sc, sh), 0.f) + xin.x;
    r.y = fmaxf(fmaf(y.y, sc, sh), 0.f) + xin.y;
    r.z = fmaxf(fmaf(y.z, sc, sh), 0.f) + xin.z;
    r.w = fmaxf(fmaf(y.w, sc, sh), 0.f) + xin.w;
    ((float4*)out)[i4] = r;
}

// ============================ launch =======================================
extern "C" void kernel_launch(void* const* d_in, const int* in_sizes, int n_in,
                              void* d_out, int out_size)
{
    const float* x     = (const float*)d_in[0];
    const float* Wq    = (const float*)d_in[1];
    const float* bq    = (const float*)d_in[2];
    const float* Wk    = (const float*)d_in[3];
    const float* bk    = (const float*)d_in[4];
    const float* Wv    = (const float*)d_in[5];
    const float* bv    = (const float*)d_in[6];
    const float* Wo    = (const float*)d_in[7];
    const float* bo    = (const float*)d_in[8];
    const float* gamma = (const float*)d_in[9];
    const float* beta  = (const float*)d_in[10];
    float* out = (float*)d_out;

    cudaFuncSetAttribute(attn_kernel,
                         cudaFuncAttributeMaxDynamicSharedMemorySize, ATTN_SMEM_BYTES);
    cudaFuncSetAttribute(qkv_kernel,
                         cudaFuncAttributeMaxDynamicSharedMemorySize, QKV_SMEM);
    cudaFuncSetAttribute(oproj_kernel,
                         cudaFuncAttributeMaxDynamicSharedMemorySize, OPROJ_SMEM);

    wsplit_kernel<<<dim3(8, 4), 256>>>(Wq, Wk, Wv, Wo);
    xsplit_kernel<<<dim3(NN/64, CC/64, BB), 256>>>(x);
    qkv_kernel<<<dim3(NN/128, BB, 3), 256, QKV_SMEM>>>(bq, bk, bv);
    attn_kernel<<<dim3(NN/128, BB), 256, ATTN_SMEM_BYTES>>>();
    oproj_kernel<<<dim3(NN/128, CC/128, BB), 256, OPROJ_SMEM>>>(bo);
    bnstat_kernel<<<1, 256>>>(gamma, beta);
    epilogue_kernel<<<(BB*CC*NN)/4/256, 256>>>(x, out);
}

// round 15
// speedup vs baseline: 1.0351x; 1.0351x over previous
#include <cuda_runtime.h>
#include <cuda_fp16.h>
#include <math.h>
#include <stdint.h>

#define BB   4
#define CC   256
#define CSd  128
#define NN   4096
#define EPSc 1e-5f
#define LOG2E 1.4426950408889634f

typedef unsigned long long ull;
typedef unsigned int u32;

// ---------------- misc helpers ----------------
__device__ __forceinline__ u32 cvt_bf2(float v1, float v0){
    u32 r; asm("cvt.rn.bf16x2.f32 %0, %1, %2;" : "=r"(r) : "f"(v1), "f"(v0)); return r;
}
__device__ __forceinline__ float ex2f(float x){
    float r; asm("ex2.approx.f32 %0, %1;" : "=f"(r) : "f"(x)); return r;
}
__device__ __forceinline__ u32 smem_u32(const void* p){
    u32 a; asm("{ .reg .u64 t; cvta.to.shared.u64 t, %1; cvt.u32.u64 %0, t; }" : "=r"(a) : "l"(p));
    return a;
}
__device__ __forceinline__ u32 packf16(float v1, float v0){
    __half2 t = __floats2half2_rn(v0, v1);
    return *(u32*)&t;
}
__device__ __forceinline__ void splitf16(float v1, float v0, u32& h, u32& l){
    __half a0 = __float2half_rn(v0), a1 = __float2half_rn(v1);
    __half2 hh = __halves2half2(a0, a1);
    h = *(u32*)&hh;
    __half2 ll = __floats2half2_rn(v0 - __half2float(a0), v1 - __half2float(a1));
    l = *(u32*)&ll;
}

// ---------------- warp-MMA + cp.async helpers ------------------------------
__device__ __forceinline__ void ldsm_x4(u32& r0,u32& r1,u32& r2,u32& r3, u32 addr){
    asm volatile("ldmatrix.sync.aligned.m8n8.x4.shared.b16 {%0,%1,%2,%3}, [%4];"
        : "=r"(r0),"=r"(r1),"=r"(r2),"=r"(r3) : "r"(addr));
}
__device__ __forceinline__ void ldsm_x4_t(u32& r0,u32& r1,u32& r2,u32& r3, u32 addr){
    asm volatile("ldmatrix.sync.aligned.m8n8.x4.trans.shared.b16 {%0,%1,%2,%3}, [%4];"
        : "=r"(r0),"=r"(r1),"=r"(r2),"=r"(r3) : "r"(addr));
}
__device__ __forceinline__ void mma_bf16(float* d, const u32* a, const u32* b){
    asm volatile("mma.sync.aligned.m16n8k16.row.col.f32.bf16.bf16.f32 "
        "{%0,%1,%2,%3}, {%4,%5,%6,%7}, {%8,%9}, {%0,%1,%2,%3};"
        : "+f"(d[0]),"+f"(d[1]),"+f"(d[2]),"+f"(d[3])
        : "r"(a[0]),"r"(a[1]),"r"(a[2]),"r"(a[3]), "r"(b[0]),"r"(b[1]));
}
__device__ __forceinline__ void mma_f16(float* d, const u32* a, const u32* b){
    asm volatile("mma.sync.aligned.m16n8k16.row.col.f32.f16.f16.f32 "
        "{%0,%1,%2,%3}, {%4,%5,%6,%7}, {%8,%9}, {%0,%1,%2,%3};"
        : "+f"(d[0]),"+f"(d[1]),"+f"(d[2]),"+f"(d[3])
        : "r"(a[0]),"r"(a[1]),"r"(a[2]),"r"(a[3]), "r"(b[0]),"r"(b[1]));
}
#define CP16(dst, src)  asm volatile("cp.async.cg.shared.global [%0], [%1], 16;" :: "r"(dst), "l"(src))
#define CP_COMMIT()     asm volatile("cp.async.commit_group;" ::: "memory")
#define CP_WAIT1()      asm volatile("cp.async.wait_group 1;" ::: "memory")
#define CP_WAIT0()      asm volatile("cp.async.wait_group 0;" ::: "memory")

// ---------------- scratch (device globals; no allocations) ----------------
__device__ __align__(16) u32 d_Qh[BB*NN*64];   // fp16 [b][n][cs] pairs
__device__ __align__(16) u32 d_Ql[BB*NN*64];
__device__ __align__(16) u32 d_Kh[BB*NN*64];   // fp16 single
__device__ __align__(16) u32 d_Vh[BB*NN*64];   // fp16 single
__device__ __align__(16) u32 d_Oh[BB*NN*64];   // bf16 splits (oproj input)
__device__ __align__(16) u32 d_Ol[BB*NN*64];
__device__ __align__(16) u32 d_xh[BB*NN*128];  // bf16 splits
__device__ __align__(16) u32 d_xl[BB*NN*128];
__device__ __align__(16) u32 d_Wh[3*CSd*128];
__device__ __align__(16) u32 d_Wl[3*CSd*128];
__device__ __align__(16) u32 d_Woh[CC*64];
__device__ __align__(16) u32 d_Wol[CC*64];
__device__ float d_Y[BB*CC*NN];
__device__ float d_ps1[128*CC];
__device__ float d_ps2[128*CC];
__device__ float d_scale[CC];
__device__ float d_shift[CC];

// ======================= Prep 1: weight splits (bf16) =======================
__global__ __launch_bounds__(256) void wsplit_kernel(
    const float* __restrict__ Wq, const float* __restrict__ Wk,
    const float* __restrict__ Wv, const float* __restrict__ Wo)
{
    const int z = blockIdx.y;
    #pragma unroll
    for (int it = 0; it < 8; it++) {
        int i = blockIdx.x*2048 + threadIdx.x + it*256;
        float v0, v1;
        if (z < 3) {
            const float* W = (z==0) ? Wq : (z==1) ? Wk : Wv;
            int cs = i >> 7, jp = i & 127;
            v0 = W[cs*CC + 2*jp]; v1 = W[cs*CC + 2*jp + 1];
        } else {
            int c = i >> 6, jp = i & 63;
            v0 = Wo[c*CSd + 2*jp]; v1 = Wo[c*CSd + 2*jp + 1];
        }
        u32 h = cvt_bf2(v1, v0);
        float f1 = __uint_as_float(h & 0xffff0000u);
        float f0 = __uint_as_float(h << 16);
        u32 l = cvt_bf2(v1 - f1, v0 - f0);
        if (z < 3) { d_Wh[z*16384 + i] = h; d_Wl[z*16384 + i] = l; }
        else       { d_Woh[i] = h;          d_Wol[i] = l; }
    }
}

// ======================= Prep 2: x transpose + split (bf16) =================
__global__ __launch_bounds__(256) void xsplit_kernel(const float* __restrict__ x)
{
    __shared__ float t[64*65];
    const int b  = blockIdx.z;
    const int c0 = blockIdx.y * 64;
    const int n0 = blockIdx.x * 64;
    const int tid = threadIdx.x;
    #pragma unroll
    for (int it = 0; it < 16; it++) {
        int idx = tid + it*256;
        int r = idx >> 6, col = idx & 63;
        t[r*65 + col] = x[(size_t)(b*CC + c0 + r)*NN + n0 + col];
    }
    __syncthreads();
    #pragma unroll
    for (int it = 0; it < 8; it++) {
        int idx = tid + it*256;
        int nl = idx >> 5, jp = idx & 31;
        float v0 = t[(2*jp)*65 + nl], v1 = t[(2*jp+1)*65 + nl];
        u32 h = cvt_bf2(v1, v0);
        float f1 = __uint_as_float(h & 0xffff0000u);
        float f0 = __uint_as_float(h << 16);
        size_t u = (size_t)(b*NN + n0 + nl)*128 + (c0 >> 1) + jp;
        d_xh[u] = h;
        d_xl[u] = cvt_bf2(v1 - f1, v0 - f0);
    }
}

// ======================= Kernel A: fused QKV projections (bf16 HMMA) ========
// One CTA per (n-tile, b): x tiles resident (4 tiles, cp.async once),
// loops z=0..2 x ch=0..1 with a shared 2-tile W buffer. Smem 6*34816 = 209KB.
#define STB 272
#define TILE_B 34816
#define QOFF_W  (4*TILE_B)
#define QKV_SMEM (6*TILE_B)

__global__ __launch_bounds__(256, 1) void qkv_kernel(
    const float* __restrict__ bq, const float* __restrict__ bk,
    const float* __restrict__ bv)
{
    extern __shared__ __align__(16) char smem[];
    const u32 sb = smem_u32(smem);
    const int b  = blockIdx.y;
    const int n0 = blockIdx.x * 128;
    const int tid = threadIdx.x;
    const int w = tid >> 5, lane = tid & 31;
    const int g = lane >> 3, lr = lane & 7, quad = lane & 3;

    // prefetch x(ch0), x(ch1): tiles [2*ch + split]
    #pragma unroll
    for (int ch = 0; ch < 2; ch++) {
        #pragma unroll
        for (int i = 0; i < 16; i++) {
            int f = tid + i*256;            // 0..4095 uint4
            int sp = f >> 11, idx = f & 2047;
            int row = idx >> 4, c16 = idx & 15;
            const u32* src = (sp ? d_xl : d_xh)
                           + (size_t)(b*NN + n0 + row)*128 + ch*64 + c16*4;
            CP16(sb + (u32)((2*ch + sp)*TILE_B + row*STB + c16*16), src);
        }
    }
    CP_COMMIT();

    const u32 aB = sb + QOFF_W + (u32)(((g>>1)*8 + lr)*STB + (g&1)*16);
    const u32 aA0 = (u32)((w*16 + (g&1)*8 + lr)*STB + (g>>1)*16);
    const int r0 = n0 + w*16 + (lane >> 2);

    for (int z = 0; z < 3; z++) {
        const float* bias = (z==0) ? bq : (z==1) ? bk : bv;
        const float qsc = (z==0) ? LOG2E : 1.0f;

        float acc[16][4];
        #pragma unroll
        for (int nb = 0; nb < 16; nb++)
            #pragma unroll
            for (int e = 0; e < 4; e++) acc[nb][e] = 0.f;

        #pragma unroll
        for (int ch = 0; ch < 2; ch++) {
            __syncthreads();   // prev (z,ch) MMAs done reading W buffer
            #pragma unroll
            for (int i = 0; i < 16; i++) {
                int f = tid + i*256;        // 0..4095 uint4
                int sp = f >> 11, idx = f & 2047;
                int row = idx >> 4, c16 = idx & 15;
                const u32* src = (sp ? d_Wl : d_Wh)
                               + (size_t)(z*CSd + row)*128 + ch*64 + c16*4;
                *(uint4*)(smem + QOFF_W + sp*TILE_B + row*STB + c16*16) = *(const uint4*)src;
            }
            if (z == 0 && ch == 0) CP_WAIT0();   // x tiles ready
            __syncthreads();

            const u32 aA = sb + 2*ch*TILE_B + aA0;
            #pragma unroll
            for (int ks = 0; ks < 8; ks++) {
                u32 ah[4], al[4];
                ldsm_x4(ah[0],ah[1],ah[2],ah[3], aA + ks*32);
                ldsm_x4(al[0],al[1],al[2],al[3], aA + TILE_B + ks*32);
                #pragma unroll
                for (int nbp = 0; nbp < 8; nbp++) {
                    u32 bh[4], blo[4];
                    ldsm_x4(bh[0],bh[1],bh[2],bh[3],     aB + nbp*16*STB + ks*32);
                    ldsm_x4(blo[0],blo[1],blo[2],blo[3], aB + TILE_B + nbp*16*STB + ks*32);
                    mma_bf16(acc[2*nbp],   ah, &bh[0]);
                    mma_bf16(acc[2*nbp],   ah, &blo[0]);
                    mma_bf16(acc[2*nbp],   al, &bh[0]);
                    mma_bf16(acc[2*nbp+1], ah, &bh[2]);
                    mma_bf16(acc[2*nbp+1], ah, &blo[2]);
                    mma_bf16(acc[2*nbp+1], al, &bh[2]);
                }
            }
        }

        #pragma unroll
        for (int nb = 0; nb < 16; nb++) {
            int col = nb*8 + quad*2;
            float b0 = __ldg(&bias[col]), b1 = __ldg(&bias[col+1]);
            #pragma unroll
            for (int half = 0; half < 2; half++) {
                float v0 = (acc[nb][2*half]   + b0) * qsc;
                float v1 = (acc[nb][2*half+1] + b1) * qsc;
                size_t u = (size_t)(b*NN + r0 + half*8)*64 + nb*4 + quad;
                if (z == 0) {
                    u32 h, l;
                    splitf16(v1, v0, h, l);
                    d_Qh[u] = h; d_Ql[u] = l;
                } else if (z == 1) {
                    d_Kh[u] = packf16(v1, v0);
                } else {
                    d_Vh[u] = packf16(v1, v0);
                }
            }
        }
    }
}

// ======================= Kernel B: fp16 HMMA flash attention (r13) ==========
// Tiles: Qh Ql (fp16 splits) + K, V (fp16 single) = 4 x 34816 = 139264 B
#define OFF_QH 0
#define OFF_QL (1*TILE_B)
#define OFF_K  (2*TILE_B)
#define OFF_V  (3*TILE_B)
#define ATTN_SMEM_BYTES (4*TILE_B)

__device__ __forceinline__ void issue_k(u32 sb, int tid, int b, int kb)
{
    #pragma unroll
    for (int i = 0; i < 8; i++) {
        int f = tid + i*256;               // 0..2047 uint4
        int row = f >> 4, c16 = f & 15;
        const u32* src = d_Kh + (size_t)(b*NN + kb + row)*64 + c16*4;
        CP16(sb + (u32)(OFF_K + row*STB + c16*16), src);
    }
}
__device__ __forceinline__ void issue_v(u32 sb, int tid, int b, int kb)
{
    #pragma unroll
    for (int i = 0; i < 8; i++) {
        int f = tid + i*256;
        int row = f >> 4, c16 = f & 15;
        const u32* src = d_Vh + (size_t)(b*NN + kb + row)*64 + c16*4;
        CP16(sb + (u32)(OFF_V + row*STB + c16*16), src);
    }
}

__global__ __launch_bounds__(256, 1) void attn_kernel()
{
    extern __shared__ __align__(16) char smem[];
    const u32 sb = smem_u32(smem);
    const int b  = blockIdx.y;
    const int q0 = blockIdx.x * 128;
    const int tid = threadIdx.x;
    const int w = tid >> 5, lane = tid & 31;
    const int g = lane >> 3, lr = lane & 7, quad = lane & 3;

    // Q tile fill (fp16 splits)
    #pragma unroll
    for (int i = 0; i < 16; i++) {
        int f = tid + i*256;
        int sp = f >> 11, idx = f & 2047;
        int row = idx >> 4, c16 = idx & 15;
        const u32* src = (sp ? d_Ql : d_Qh) + (size_t)(b*NN + q0 + row)*64 + c16*4;
        *(uint4*)(smem + (sp ? OFF_QL : OFF_QH) + row*STB + c16*16) = *(const uint4*)src;
    }

    const u32 aQh = sb + OFF_QH + (u32)((w*16 + (g&1)*8 + lr)*STB + (g>>1)*16);
    const u32 aQl = aQh + TILE_B;
    const u32 aK  = sb + OFF_K + (u32)(((g>>1)*8 + lr)*STB + (g&1)*16);
    const u32 aV  = sb + OFF_V + (u32)(((g&1)*8 + lr)*STB + (g>>1)*16);

    float o[16][4];
    #pragma unroll
    for (int nb = 0; nb < 16; nb++)
        #pragma unroll
        for (int e = 0; e < 4; e++) o[nb][e] = 0.f;
    float m0 = -1e30f, m1 = -1e30f, l0 = 0.f, l1 = 0.f;

    issue_k(sb, tid, b, 0); CP_COMMIT();
    issue_v(sb, tid, b, 0); CP_COMMIT();

    for (int kt = 0; kt < NN/128; kt++) {
        CP_WAIT1();                 // K(kt) ready
        __syncthreads();

        // ---- S = Q.K^T (fp16 2-split: Qh.K + Ql.K) ----
        float s[16][4];
        #pragma unroll
        for (int nb = 0; nb < 16; nb++)
            #pragma unroll
            for (int e = 0; e < 4; e++) s[nb][e] = 0.f;
        #pragma unroll
        for (int ks = 0; ks < 8; ks++) {
            u32 ah[4], al[4];
            ldsm_x4(ah[0],ah[1],ah[2],ah[3], aQh + ks*32);
            ldsm_x4(al[0],al[1],al[2],al[3], aQl + ks*32);
            #pragma unroll
            for (int nbp = 0; nbp < 8; nbp++) {
                u32 kh[4];
                ldsm_x4(kh[0],kh[1],kh[2],kh[3], aK + nbp*16*STB + ks*32);
                mma_f16(s[2*nbp],   ah, &kh[0]);
                mma_f16(s[2*nbp],   al, &kh[0]);
                mma_f16(s[2*nbp+1], ah, &kh[2]);
                mma_f16(s[2*nbp+1], al, &kh[2]);
            }
        }
        __syncthreads();            // K reads done
        if (kt + 1 < NN/128) issue_k(sb, tid, b, (kt+1)*128);
        CP_COMMIT();

        // ---- row max + accumulator rescale ----
        float tm0 = -1e30f, tm1 = -1e30f;
        #pragma unroll
        for (int nb = 0; nb < 16; nb++) {
            tm0 = fmaxf(tm0, fmaxf(s[nb][0], s[nb][1]));
            tm1 = fmaxf(tm1, fmaxf(s[nb][2], s[nb][3]));
        }
        tm0 = fmaxf(tm0, __shfl_xor_sync(0xffffffffu, tm0, 1));
        tm0 = fmaxf(tm0, __shfl_xor_sync(0xffffffffu, tm0, 2));
        tm1 = fmaxf(tm1, __shfl_xor_sync(0xffffffffu, tm1, 1));
        tm1 = fmaxf(tm1, __shfl_xor_sync(0xffffffffu, tm1, 2));
        float nm0 = fmaxf(m0, tm0), nm1 = fmaxf(m1, tm1);
        float rs0 = ex2f(m0 - nm0), rs1 = ex2f(m1 - nm1);
        m0 = nm0; m1 = nm1;
        #pragma unroll
        for (int nb = 0; nb < 16; nb++) {
            o[nb][0] *= rs0; o[nb][1] *= rs0;
            o[nb][2] *= rs1; o[nb][3] *= rs1;
        }

        CP_WAIT1();                 // V(kt) ready (K(kt+1) in flight)
        __syncthreads();

        // ---- fused exp + fp16 pack + PV (single split) ----
        float ps0 = 0.f, ps1 = 0.f;
        #pragma unroll
        for (int ks2 = 0; ks2 < 8; ks2++) {
            int na = 2*ks2, nbb = 2*ks2 + 1;
            float e00 = ex2f(s[na][0]  - nm0), e01 = ex2f(s[na][1]  - nm0);
            float e02 = ex2f(s[na][2]  - nm1), e03 = ex2f(s[na][3]  - nm1);
            float e10 = ex2f(s[nbb][0] - nm0), e11 = ex2f(s[nbb][1] - nm0);
            float e12 = ex2f(s[nbb][2] - nm1), e13 = ex2f(s[nbb][3] - nm1);
            ps0 += e00 + e01 + e10 + e11;
            ps1 += e02 + e03 + e12 + e13;
            u32 pah[4];
            pah[0] = packf16(e01, e00);
            pah[1] = packf16(e03, e02);
            pah[2] = packf16(e11, e10);
            pah[3] = packf16(e13, e12);
            #pragma unroll
            for (int nbp = 0; nbp < 8; nbp++) {
                u32 vh[4];
                ldsm_x4_t(vh[0],vh[1],vh[2],vh[3], aV + ks2*16*STB + nbp*32);
                mma_f16(o[2*nbp],   pah, &vh[0]);
                mma_f16(o[2*nbp+1], pah, &vh[2]);
            }
        }
        ps0 += __shfl_xor_sync(0xffffffffu, ps0, 1);
        ps0 += __shfl_xor_sync(0xffffffffu, ps0, 2);
        ps1 += __shfl_xor_sync(0xffffffffu, ps1, 1);
        ps1 += __shfl_xor_sync(0xffffffffu, ps1, 2);
        l0 = l0*rs0 + ps0;
        l1 = l1*rs1 + ps1;

        __syncthreads();            // V reads done
        if (kt + 1 < NN/128) issue_v(sb, tid, b, (kt+1)*128);
        CP_COMMIT();
    }

    // ---- epilogue: normalize, bf16 hi/lo split, write d_Oh/d_Ol ----
    float inv0 = 1.0f / l0, inv1 = 1.0f / l1;
    int r0g = q0 + w*16 + (lane >> 2);
    #pragma unroll
    for (int nb = 0; nb < 16; nb++) {
        #pragma unroll
        for (int half = 0; half < 2; half++) {
            float v0 = o[nb][2*half]   * (half ? inv1 : inv0);
            float v1 = o[nb][2*half+1] * (half ? inv1 : inv0);
            u32 h = cvt_bf2(v1, v0);
            float f1 = __uint_as_float(h & 0xffff0000u);
            float f0 = __uint_as_float(h << 16);
            size_t u = (size_t)(b*NN + r0g + half*8)*64 + nb*4 + quad;
            d_Oh[u] = h;
            d_Ol[u] = cvt_bf2(v1 - f1, v0 - f0);
        }
    }
}

// ======================= Kernel C: output projection (bf16 HMMA) ============
#define OPROJ_SMEM (4*TILE_B + 128*132*4)

__global__ __launch_bounds__(256, 1) void oproj_kernel(const float* __restrict__ bo)
{
    extern __shared__ __align__(16) char smem[];
    const u32 sb = smem_u32(smem);
    const int b  = blockIdx.z;
    const int c0 = blockIdx.y * 128;
    const int n0 = blockIdx.x * 128;
    const int tid = threadIdx.x;
    const int w = tid >> 5, lane = tid & 31;
    const int g = lane >> 3, lr = lane & 7, quad = lane & 3;

    #pragma unroll
    for (int i = 0; i < 32; i++) {
        int f = tid + i*256;
        int t4 = f >> 11, idx = f & 2047;
        int row = idx >> 4, c16 = idx & 15;
        const u32* src;
        if (t4 < 2)
            src = (t4 ? d_Ol : d_Oh) + (size_t)(b*NN + n0 + row)*64 + c16*4;
        else
            src = ((t4==2) ? d_Woh : d_Wol) + (size_t)(c0 + row)*64 + c16*4;
        *(uint4*)(smem + t4*TILE_B + row*STB + c16*16) = *(const uint4*)src;
    }
    __syncthreads();

    const u32 aA = sb + (u32)((w*16 + (g&1)*8 + lr)*STB + (g>>1)*16);
    const u32 aB = sb + 2*TILE_B + (u32)(((g>>1)*8 + lr)*STB + (g&1)*16);

    float acc[16][4];
    #pragma unroll
    for (int nb = 0; nb < 16; nb++)
        #pragma unroll
        for (int e = 0; e < 4; e++) acc[nb][e] = 0.f;

    #pragma unroll
    for (int ks = 0; ks < 8; ks++) {
        u32 ah[4], al[4];
        ldsm_x4(ah[0],ah[1],ah[2],ah[3], aA + ks*32);
        ldsm_x4(al[0],al[1],al[2],al[3], aA + TILE_B + ks*32);
        #pragma unroll
        for (int nbp = 0; nbp < 8; nbp++) {
            u32 bh[4], blo[4];
            ldsm_x4(bh[0],bh[1],bh[2],bh[3],     aB + nbp*16*STB + ks*32);
            ldsm_x4(blo[0],blo[1],blo[2],blo[3], aB + TILE_B + nbp*16*STB + ks*32);
            mma_bf16(acc[2*nbp],   ah, &bh[0]);
            mma_bf16(acc[2*nbp],   ah, &blo[0]);
            mma_bf16(acc[2*nbp],   al, &bh[0]);
            mma_bf16(acc[2*nbp+1], ah, &bh[2]);
            mma_bf16(acc[2*nbp+1], ah, &blo[2]);
            mma_bf16(acc[2*nbp+1], al, &bh[2]);
        }
    }
    __syncthreads();

    float* ys = (float*)(smem + 4*TILE_B);
    int r0 = w*16 + (lane >> 2);
    #pragma unroll
    for (int nb = 0; nb < 16; nb++) {
        int col = nb*8 + quad*2;
        float b0 = __ldg(&bo[c0+col]), b1 = __ldg(&bo[c0+col+1]);
        ys[col*132 + r0]         = acc[nb][0] + b0;
        ys[(col+1)*132 + r0]     = acc[nb][1] + b1;
        ys[col*132 + r0 + 8]     = acc[nb][2] + b0;
        ys[(col+1)*132 + r0 + 8] = acc[nb][3] + b1;
    }
    __syncthreads();

    {
        int c = tid >> 1, hn = (tid & 1) * 64;
        float s = 0.f, s2 = 0.f;
        #pragma unroll 8
        for (int j = 0; j < 64; j++) {
            float v = ys[c*132 + hn + j];
            s += v; s2 += v*v;
        }
        s  += __shfl_xor_sync(0xffffffffu, s, 1);
        s2 += __shfl_xor_sync(0xffffffffu, s2, 1);
        if (!(tid & 1)) {
            int j = b*32 + blockIdx.x;
            d_ps1[(size_t)j*CC + c0 + c] = s;
            d_ps2[(size_t)j*CC + c0 + c] = s2;
        }
    }

    #pragma unroll
    for (int i = 0; i < 16; i++) {
        int f = tid + i*256;
        int row = f >> 5, q4 = f & 31;
        *(float4*)&d_Y[(size_t)(b*CC + c0 + row)*NN + n0 + q4*4] =
            *(float4*)&ys[row*132 + q4*4];
    }
}

// ======================= Kernel D: BN stats from partials ===================
__global__ __launch_bounds__(256) void bnstat_kernel(
    const float* __restrict__ gamma, const float* __restrict__ beta)
{
    const int c = threadIdx.x;
    float s = 0.f, s2 = 0.f;
    #pragma unroll 8
    for (int j = 0; j < 128; j++) {
        s  += d_ps1[(size_t)j*CC + c];
        s2 += d_ps2[(size_t)j*CC + c];
    }
    float mean = s  * (1.f/16384.f);
    float var  = s2 * (1.f/16384.f) - mean*mean;
    float sc = gamma[c] * rsqrtf(var + EPSc);
    d_scale[c] = sc;
    d_shift[c] = beta[c] - mean*sc;
}

// ======================= Kernel E: BN affine + ReLU + residual ==============
__global__ __launch_bounds__(256) void epilogue_kernel(
    const float* __restrict__ x, float* __restrict__ out)
{
    int i4 = blockIdx.x*256 + threadIdx.x;
    int idx = i4 * 4;
    int c = (idx >> 12) & 255;
    float sc = d_scale[c], sh = d_shift[c];
    float4 y   = *(const float4*)&d_Y[idx];
    float4 xin = ((const float4*)x)[i4];
    float4 r;
    r.x = fmaxf(fmaf(y.x, sc, sh), 0.f) + xin.x;
    r.y = fmaxf(fmaf(y.y, sc, sh), 0.f) + xin.y;
    r.z = fmaxf(fmaf(y.z, sc, sh), 0.f) + xin.z;
    r.w = fmaxf(fmaf(y.w, sc, sh), 0.f) + xin.w;
    ((float4*)out)[i4] = r;
}

// ============================ launch =======================================
extern "C" void kernel_launch(void* const* d_in, const int* in_sizes, int n_in,
                              void* d_out, int out_size)
{
    const float* x     = (const float*)d_in[0];
    const float* Wq    = (const float*)d_in[1];
    const float* bq    = (const float*)d_in[2];
    const float* Wk    = (const float*)d_in[3];
    const float* bk    = (const float*)d_in[4];
    const float* Wv    = (const float*)d_in[5];
    const float* bv    = (const float*)d_in[6];
    const float* Wo    = (const float*)d_in[7];
    const float* bo    = (const float*)d_in[8];
    const float* gamma = (const float*)d_in[9];
    const float* beta  = (const float*)d_in[10];
    float* out = (float*)d_out;

    cudaFuncSetAttribute(attn_kernel,
                         cudaFuncAttributeMaxDynamicSharedMemorySize, ATTN_SMEM_BYTES);
    cudaFuncSetAttribute(qkv_kernel,
                         cudaFuncAttributeMaxDynamicSharedMemorySize, QKV_SMEM);
    cudaFuncSetAttribute(oproj_kernel,
                         cudaFuncAttributeMaxDynamicSharedMemorySize, OPROJ_SMEM);

    wsplit_kernel<<<dim3(8, 4), 256>>>(Wq, Wk, Wv, Wo);
    xsplit_kernel<<<dim3(NN/64, CC/64, BB), 256>>>(x);
    qkv_kernel<<<dim3(NN/128, BB), 256, QKV_SMEM>>>(bq, bk, bv);
    attn_kernel<<<dim3(NN/128, BB), 256, ATTN_SMEM_BYTES>>>();
    oproj_kernel<<<dim3(NN/128, CC/128, BB), 256, OPROJ_SMEM>>>(bo);
    bnstat_kernel<<<1, 256>>>(gamma, beta);
    epilogue_kernel<<<(BB*CC*NN)/4/256, 256>>>(x, out);
}

// round 17
// speedup vs baseline: 1.0635x; 1.0275x over previous
#include <cuda_runtime.h>
#include <cuda_fp16.h>
#include <math.h>
#include <stdint.h>

#define BB   4
#define CC   256
#define CSd  128
#define NN   4096
#define EPSc 1e-5f
#define LOG2E 1.4426950408889634f

typedef unsigned long long ull;
typedef unsigned int u32;

// ---------------- misc helpers ----------------
__device__ __forceinline__ u32 cvt_bf2(float v1, float v0){
    u32 r; asm("cvt.rn.bf16x2.f32 %0, %1, %2;" : "=r"(r) : "f"(v1), "f"(v0)); return r;
}
__device__ __forceinline__ float ex2f(float x){
    float r; asm("ex2.approx.f32 %0, %1;" : "=f"(r) : "f"(x)); return r;
}
__device__ __forceinline__ u32 smem_u32(const void* p){
    u32 a; asm("{ .reg .u64 t; cvta.to.shared.u64 t, %1; cvt.u32.u64 %0, t; }" : "=r"(a) : "l"(p));
    return a;
}
__device__ __forceinline__ u32 packf16(float v1, float v0){
    __half2 t = __floats2half2_rn(v0, v1);
    return *(u32*)&t;
}
__device__ __forceinline__ void splitf16(float v1, float v0, u32& h, u32& l){
    __half a0 = __float2half_rn(v0), a1 = __float2half_rn(v1);
    __half2 hh = __halves2half2(a0, a1);
    h = *(u32*)&hh;
    __half2 ll = __floats2half2_rn(v0 - __half2float(a0), v1 - __half2float(a1));
    l = *(u32*)&ll;
}

// ---------------- warp-MMA + cp.async helpers ------------------------------
__device__ __forceinline__ void ldsm_x4(u32& r0,u32& r1,u32& r2,u32& r3, u32 addr){
    asm volatile("ldmatrix.sync.aligned.m8n8.x4.shared.b16 {%0,%1,%2,%3}, [%4];"
        : "=r"(r0),"=r"(r1),"=r"(r2),"=r"(r3) : "r"(addr));
}
__device__ __forceinline__ void ldsm_x4_t(u32& r0,u32& r1,u32& r2,u32& r3, u32 addr){
    asm volatile("ldmatrix.sync.aligned.m8n8.x4.trans.shared.b16 {%0,%1,%2,%3}, [%4];"
        : "=r"(r0),"=r"(r1),"=r"(r2),"=r"(r3) : "r"(addr));
}
__device__ __forceinline__ void mma_bf16(float* d, const u32* a, const u32* b){
    asm volatile("mma.sync.aligned.m16n8k16.row.col.f32.bf16.bf16.f32 "
        "{%0,%1,%2,%3}, {%4,%5,%6,%7}, {%8,%9}, {%0,%1,%2,%3};"
        : "+f"(d[0]),"+f"(d[1]),"+f"(d[2]),"+f"(d[3])
        : "r"(a[0]),"r"(a[1]),"r"(a[2]),"r"(a[3]), "r"(b[0]),"r"(b[1]));
}
__device__ __forceinline__ void mma_f16(float* d, const u32* a, const u32* b){
    asm volatile("mma.sync.aligned.m16n8k16.row.col.f32.f16.f16.f32 "
        "{%0,%1,%2,%3}, {%4,%5,%6,%7}, {%8,%9}, {%0,%1,%2,%3};"
        : "+f"(d[0]),"+f"(d[1]),"+f"(d[2]),"+f"(d[3])
        : "r"(a[0]),"r"(a[1]),"r"(a[2]),"r"(a[3]), "r"(b[0]),"r"(b[1]));
}
#define CP16(dst, src)  asm volatile("cp.async.cg.shared.global [%0], [%1], 16;" :: "r"(dst), "l"(src))
#define CP_COMMIT()     asm volatile("cp.async.commit_group;" ::: "memory")
#define CP_WAIT1()      asm volatile("cp.async.wait_group 1;" ::: "memory")

// ---------------- scratch (device globals; no allocations) ----------------
__device__ __align__(16) u32 d_Qh[BB*NN*64];   // fp16 [b][n][cs] pairs
__device__ __align__(16) u32 d_Ql[BB*NN*64];
__device__ __align__(16) u32 d_Kh[BB*NN*64];   // fp16 single
__device__ __align__(16) u32 d_Vh[BB*NN*64];   // fp16 single
__device__ __align__(16) u32 d_Oh[BB*NN*64];   // bf16 splits (oproj input)
__device__ __align__(16) u32 d_Ol[BB*NN*64];
__device__ __align__(16) u32 d_Wh[3*CSd*128];  // W q/k/v bf16 splits
__device__ __align__(16) u32 d_Wl[3*CSd*128];
__device__ __align__(16) u32 d_Woh[CC*64];
__device__ __align__(16) u32 d_Wol[CC*64];
__device__ float d_Y[BB*CC*NN];
__device__ float d_ps1[128*CC];
__device__ float d_ps2[128*CC];
__device__ float d_scale[CC];
__device__ float d_shift[CC];

// ======================= Prep: weight splits (bf16) =========================
__global__ __launch_bounds__(256) void wsplit_kernel(
    const float* __restrict__ Wq, const float* __restrict__ Wk,
    const float* __restrict__ Wv, const float* __restrict__ Wo)
{
    const int z = blockIdx.y;
    #pragma unroll
    for (int it = 0; it < 8; it++) {
        int i = blockIdx.x*2048 + threadIdx.x + it*256;
        float v0, v1;
        if (z < 3) {
            const float* W = (z==0) ? Wq : (z==1) ? Wk : Wv;
            int cs = i >> 7, jp = i & 127;
            v0 = W[cs*CC + 2*jp]; v1 = W[cs*CC + 2*jp + 1];
        } else {
            int c = i >> 6, jp = i & 63;
            v0 = Wo[c*CSd + 2*jp]; v1 = Wo[c*CSd + 2*jp + 1];
        }
        u32 h = cvt_bf2(v1, v0);
        float f1 = __uint_as_float(h & 0xffff0000u);
        float f0 = __uint_as_float(h << 16);
        u32 l = cvt_bf2(v1 - f1, v0 - f0);
        if (z < 3) { d_Wh[z*16384 + i] = h; d_Wl[z*16384 + i] = l; }
        else       { d_Woh[i] = h;          d_Wol[i] = l; }
    }
}

// ======================= Kernel A: fused QKV (x transpose+split in-CTA) =====
// One CTA per (n-tile, b). Each ch chunk = 128 channels: staged fp32
// transposed in the W area (t[128 n][130]), split to bf16 hi/lo A-tiles
// (64 u32 per row), then z-loop 0..2 with shared 2-tile W buffer.
#define STB 272
#define TILE_B 34816
#define QOFF_W  (4*TILE_B)
#define QKV_SMEM (6*TILE_B)

__global__ __launch_bounds__(256, 1) void qkv_kernel(
    const float* __restrict__ x,
    const float* __restrict__ bq, const float* __restrict__ bk,
    const float* __restrict__ bv)
{
    extern __shared__ __align__(16) char smem[];
    const u32 sb = smem_u32(smem);
    const int b  = blockIdx.y;
    const int n0 = blockIdx.x * 128;
    const int tid = threadIdx.x;
    const int w = tid >> 5, lane = tid & 31;
    const int g = lane >> 3, lr = lane & 7, quad = lane & 3;

    // ---- build x A-tiles: stage fp32 transposed, then bf16 hi/lo split ----
    float* t = (float*)(smem + QOFF_W);            // staging [128 n][130] fp32
    #pragma unroll
    for (int ch = 0; ch < 2; ch++) {
        __syncthreads();                            // staging free
        #pragma unroll
        for (int it = 0; it < 64; it++) {
            int f = tid + it*256;                   // 0..16383
            int n = f & 127, c = f >> 7;            // c 0..127, coalesced over n
            t[n*130 + c] = x[(size_t)(b*CC + ch*128 + c)*NN + n0 + n];
        }
        __syncthreads();
        u32* th = (u32*)(smem + 2*ch*TILE_B);       // hi tile
        u32* tl = (u32*)(smem + (2*ch+1)*TILE_B);   // lo tile
        #pragma unroll
        for (int it = 0; it < 32; it++) {
            int f = tid + it*256;                   // 0..8191
            int n = f >> 6, jp = f & 63;            // jp 0..63 u32 per row
            float2 v = *(float2*)&t[n*130 + 2*jp];
            u32 h = cvt_bf2(v.y, v.x);
            float f1 = __uint_as_float(h & 0xffff0000u);
            float f0 = __uint_as_float(h << 16);
            th[n*68 + jp] = h;
            tl[n*68 + jp] = cvt_bf2(v.y - f1, v.x - f0);
        }
    }

    const u32 aB = sb + QOFF_W + (u32)(((g>>1)*8 + lr)*STB + (g&1)*16);
    const u32 aA0 = (u32)((w*16 + (g&1)*8 + lr)*STB + (g>>1)*16);
    const int r0 = n0 + w*16 + (lane >> 2);

    for (int z = 0; z < 3; z++) {
        const float* bias = (z==0) ? bq : (z==1) ? bk : bv;
        const float qsc = (z==0) ? LOG2E : 1.0f;

        float acc[16][4];
        #pragma unroll
        for (int nb = 0; nb < 16; nb++)
            #pragma unroll
            for (int e = 0; e < 4; e++) acc[nb][e] = 0.f;

        #pragma unroll
        for (int ch = 0; ch < 2; ch++) {
            __syncthreads();   // prev MMAs (or transpose) done with W area
            #pragma unroll
            for (int i = 0; i < 16; i++) {
                int f = tid + i*256;
                int sp = f >> 11, idx = f & 2047;
                int row = idx >> 4, c16 = idx & 15;
                const u32* src = (sp ? d_Wl : d_Wh)
                               + (size_t)(z*CSd + row)*128 + ch*64 + c16*4;
                *(uint4*)(smem + QOFF_W + sp*TILE_B + row*STB + c16*16) = *(const uint4*)src;
            }
            __syncthreads();

            const u32 aA = sb + 2*ch*TILE_B + aA0;
            #pragma unroll
            for (int ks = 0; ks < 8; ks++) {
                u32 ah[4], al[4];
                ldsm_x4(ah[0],ah[1],ah[2],ah[3], aA + ks*32);
                ldsm_x4(al[0],al[1],al[2],al[3], aA + TILE_B + ks*32);
                #pragma unroll
                for (int nbp = 0; nbp < 8; nbp++) {
                    u32 bh[4], blo[4];
                    ldsm_x4(bh[0],bh[1],bh[2],bh[3],     aB + nbp*16*STB + ks*32);
                    ldsm_x4(blo[0],blo[1],blo[2],blo[3], aB + TILE_B + nbp*16*STB + ks*32);
                    mma_bf16(acc[2*nbp],   ah, &bh[0]);
                    mma_bf16(acc[2*nbp],   ah, &blo[0]);
                    mma_bf16(acc[2*nbp],   al, &bh[0]);
                    mma_bf16(acc[2*nbp+1], ah, &bh[2]);
                    mma_bf16(acc[2*nbp+1], ah, &blo[2]);
                    mma_bf16(acc[2*nbp+1], al, &bh[2]);
                }
            }
        }

        #pragma unroll
        for (int nb = 0; nb < 16; nb++) {
            int col = nb*8 + quad*2;
            float b0 = __ldg(&bias[col]), b1 = __ldg(&bias[col+1]);
            #pragma unroll
            for (int half = 0; half < 2; half++) {
                float v0 = (acc[nb][2*half]   + b0) * qsc;
                float v1 = (acc[nb][2*half+1] + b1) * qsc;
                size_t u = (size_t)(b*NN + r0 + half*8)*64 + nb*4 + quad;
                if (z == 0) {
                    u32 h, l;
                    splitf16(v1, v0, h, l);
                    d_Qh[u] = h; d_Ql[u] = l;
                } else if (z == 1) {
                    d_Kh[u] = packf16(v1, v0);
                } else {
                    d_Vh[u] = packf16(v1, v0);
                }
            }
        }
    }
}

// ======================= Kernel B: fp16 HMMA flash attention ================
#define OFF_QH 0
#define OFF_QL (1*TILE_B)
#define OFF_K  (2*TILE_B)
#define OFF_V  (3*TILE_B)
#define ATTN_SMEM_BYTES (4*TILE_B)

__device__ __forceinline__ void issue_k(u32 sb, int tid, int b, int kb)
{
    #pragma unroll
    for (int i = 0; i < 8; i++) {
        int f = tid + i*256;
        int row = f >> 4, c16 = f & 15;
        const u32* src = d_Kh + (size_t)(b*NN + kb + row)*64 + c16*4;
        CP16(sb + (u32)(OFF_K + row*STB + c16*16), src);
    }
}
__device__ __forceinline__ void issue_v(u32 sb, int tid, int b, int kb)
{
    #pragma unroll
    for (int i = 0; i < 8; i++) {
        int f = tid + i*256;
        int row = f >> 4, c16 = f & 15;
        const u32* src = d_Vh + (size_t)(b*NN + kb + row)*64 + c16*4;
        CP16(sb + (u32)(OFF_V + row*STB + c16*16), src);
    }
}

__global__ __launch_bounds__(256, 1) void attn_kernel()
{
    extern __shared__ __align__(16) char smem[];
    const u32 sb = smem_u32(smem);
    const int b  = blockIdx.y;
    const int q0 = blockIdx.x * 128;
    const int tid = threadIdx.x;
    const int w = tid >> 5, lane = tid & 31;
    const int g = lane >> 3, lr = lane & 7, quad = lane & 3;

    #pragma unroll
    for (int i = 0; i < 16; i++) {
        int f = tid + i*256;
        int sp = f >> 11, idx = f & 2047;
        int row = idx >> 4, c16 = idx & 15;
        const u32* src = (sp ? d_Ql : d_Qh) + (size_t)(b*NN + q0 + row)*64 + c16*4;
        *(uint4*)(smem + (sp ? OFF_QL : OFF_QH) + row*STB + c16*16) = *(const uint4*)src;
    }

    const u32 aQh = sb + OFF_QH + (u32)((w*16 + (g&1)*8 + lr)*STB + (g>>1)*16);
    const u32 aQl = aQh + TILE_B;
    const u32 aK  = sb + OFF_K + (u32)(((g>>1)*8 + lr)*STB + (g&1)*16);
    const u32 aV  = sb + OFF_V + (u32)(((g&1)*8 + lr)*STB + (g>>1)*16);

    float o[16][4];
    #pragma unroll
    for (int nb = 0; nb < 16; nb++)
        #pragma unroll
        for (int e = 0; e < 4; e++) o[nb][e] = 0.f;
    float m0 = -1e30f, m1 = -1e30f, l0 = 0.f, l1 = 0.f;

    issue_k(sb, tid, b, 0); CP_COMMIT();
    issue_v(sb, tid, b, 0); CP_COMMIT();

    for (int kt = 0; kt < NN/128; kt++) {
        CP_WAIT1();
        __syncthreads();

        float s[16][4];
        #pragma unroll
        for (int nb = 0; nb < 16; nb++)
            #pragma unroll
            for (int e = 0; e < 4; e++) s[nb][e] = 0.f;
        #pragma unroll
        for (int ks = 0; ks < 8; ks++) {
            u32 ah[4], al[4];
            ldsm_x4(ah[0],ah[1],ah[2],ah[3], aQh + ks*32);
            ldsm_x4(al[0],al[1],al[2],al[3], aQl + ks*32);
            #pragma unroll
            for (int nbp = 0; nbp < 8; nbp++) {
                u32 kh[4];
                ldsm_x4(kh[0],kh[1],kh[2],kh[3], aK + nbp*16*STB + ks*32);
                mma_f16(s[2*nbp],   ah, &kh[0]);
                mma_f16(s[2*nbp],   al, &kh[0]);
                mma_f16(s[2*nbp+1], ah, &kh[2]);
                mma_f16(s[2*nbp+1], al, &kh[2]);
            }
        }
        __syncthreads();
        if (kt + 1 < NN/128) issue_k(sb, tid, b, (kt+1)*128);
        CP_COMMIT();

        float tm0 = -1e30f, tm1 = -1e30f;
        #pragma unroll
        for (int nb = 0; nb < 16; nb++) {
            tm0 = fmaxf(tm0, fmaxf(s[nb][0], s[nb][1]));
            tm1 = fmaxf(tm1, fmaxf(s[nb][2], s[nb][3]));
        }
        tm0 = fmaxf(tm0, __shfl_xor_sync(0xffffffffu, tm0, 1));
        tm0 = fmaxf(tm0, __shfl_xor_sync(0xffffffffu, tm0, 2));
        tm1 = fmaxf(tm1, __shfl_xor_sync(0xffffffffu, tm1, 1));
        tm1 = fmaxf(tm1, __shfl_xor_sync(0xffffffffu, tm1, 2));
        float nm0 = fmaxf(m0, tm0), nm1 = fmaxf(m1, tm1);
        float rs0 = ex2f(m0 - nm0), rs1 = ex2f(m1 - nm1);
        m0 = nm0; m1 = nm1;
        #pragma unroll
        for (int nb = 0; nb < 16; nb++) {
            o[nb][0] *= rs0; o[nb][1] *= rs0;
            o[nb][2] *= rs1; o[nb][3] *= rs1;
        }

        CP_WAIT1();
        __syncthreads();

        float ps0 = 0.f, ps1 = 0.f;
        #pragma unroll
        for (int ks2 = 0; ks2 < 8; ks2++) {
            int na = 2*ks2, nbb = 2*ks2 + 1;
            float e00 = ex2f(s[na][0]  - nm0), e01 = ex2f(s[na][1]  - nm0);
            float e02 = ex2f(s[na][2]  - nm1), e03 = ex2f(s[na][3]  - nm1);
            float e10 = ex2f(s[nbb][0] - nm0), e11 = ex2f(s[nbb][1] - nm0);
            float e12 = ex2f(s[nbb][2] - nm1), e13 = ex2f(s[nbb][3] - nm1);
            ps0 += e00 + e01 + e10 + e11;
            ps1 += e02 + e03 + e12 + e13;
            u32 pah[4];
            pah[0] = packf16(e01, e00);
            pah[1] = packf16(e03, e02);
            pah[2] = packf16(e11, e10);
            pah[3] = packf16(e13, e12);
            #pragma unroll
            for (int nbp = 0; nbp < 8; nbp++) {
                u32 vh[4];
                ldsm_x4_t(vh[0],vh[1],vh[2],vh[3], aV + ks2*16*STB + nbp*32);
                mma_f16(o[2*nbp],   pah, &vh[0]);
                mma_f16(o[2*nbp+1], pah, &vh[2]);
            }
        }
        ps0 += __shfl_xor_sync(0xffffffffu, ps0, 1);
        ps0 += __shfl_xor_sync(0xffffffffu, ps0, 2);
        ps1 += __shfl_xor_sync(0xffffffffu, ps1, 1);
        ps1 += __shfl_xor_sync(0xffffffffu, ps1, 2);
        l0 = l0*rs0 + ps0;
        l1 = l1*rs1 + ps1;

        __syncthreads();
        if (kt + 1 < NN/128) issue_v(sb, tid, b, (kt+1)*128);
        CP_COMMIT();
    }

    float inv0 = 1.0f / l0, inv1 = 1.0f / l1;
    int r0g = q0 + w*16 + (lane >> 2);
    #pragma unroll
    for (int nb = 0; nb < 16; nb++) {
        #pragma unroll
        for (int half = 0; half < 2; half++) {
            float v0 = o[nb][2*half]   * (half ? inv1 : inv0);
            float v1 = o[nb][2*half+1] * (half ? inv1 : inv0);
            u32 h = cvt_bf2(v1, v0);
            float f1 = __uint_as_float(h & 0xffff0000u);
            float f0 = __uint_as_float(h << 16);
            size_t u = (size_t)(b*NN + r0g + half*8)*64 + nb*4 + quad;
            d_Oh[u] = h;
            d_Ol[u] = cvt_bf2(v1 - f1, v0 - f0);
        }
    }
}

// ======================= Kernel C: output projection (bf16 HMMA) ============
#define OPROJ_SMEM (4*TILE_B + 128*132*4)

__global__ __launch_bounds__(256, 1) void oproj_kernel(const float* __restrict__ bo)
{
    extern __shared__ __align__(16) char smem[];
    const u32 sb = smem_u32(smem);
    const int b  = blockIdx.z;
    const int c0 = blockIdx.y * 128;
    const int n0 = blockIdx.x * 128;
    const int tid = threadIdx.x;
    const int w = tid >> 5, lane = tid & 31;
    const int g = lane >> 3, lr = lane & 7, quad = lane & 3;

    #pragma unroll
    for (int i = 0; i < 32; i++) {
        int f = tid + i*256;
        int t4 = f >> 11, idx = f & 2047;
        int row = idx >> 4, c16 = idx & 15;
        const u32* src;
        if (t4 < 2)
            src = (t4 ? d_Ol : d_Oh) + (size_t)(b*NN + n0 + row)*64 + c16*4;
        else
            src = ((t4==2) ? d_Woh : d_Wol) + (size_t)(c0 + row)*64 + c16*4;
        *(uint4*)(smem + t4*TILE_B + row*STB + c16*16) = *(const uint4*)src;
    }
    __syncthreads();

    const u32 aA = sb + (u32)((w*16 + (g&1)*8 + lr)*STB + (g>>1)*16);
    const u32 aB = sb + 2*TILE_B + (u32)(((g>>1)*8 + lr)*STB + (g&1)*16);

    float acc[16][4];
    #pragma unroll
    for (int nb = 0; nb < 16; nb++)
        #pragma unroll
        for (int e = 0; e < 4; e++) acc[nb][e] = 0.f;

    #pragma unroll
    for (int ks = 0; ks < 8; ks++) {
        u32 ah[4], al[4];
        ldsm_x4(ah[0],ah[1],ah[2],ah[3], aA + ks*32);
        ldsm_x4(al[0],al[1],al[2],al[3], aA + TILE_B + ks*32);
        #pragma unroll
        for (int nbp = 0; nbp < 8; nbp++) {
            u32 bh[4], blo[4];
            ldsm_x4(bh[0],bh[1],bh[2],bh[3],     aB + nbp*16*STB + ks*32);
            ldsm_x4(blo[0],blo[1],blo[2],blo[3], aB + TILE_B + nbp*16*STB + ks*32);
            mma_bf16(acc[2*nbp],   ah, &bh[0]);
            mma_bf16(acc[2*nbp],   ah, &blo[0]);
            mma_bf16(acc[2*nbp],   al, &bh[0]);
            mma_bf16(acc[2*nbp+1], ah, &bh[2]);
            mma_bf16(acc[2*nbp+1], ah, &blo[2]);
            mma_bf16(acc[2*nbp+1], al, &bh[2]);
        }
    }
    __syncthreads();

    float* ys = (float*)(smem + 4*TILE_B);
    int r0 = w*16 + (lane >> 2);
    #pragma unroll
    for (int nb = 0; nb < 16; nb++) {
        int col = nb*8 + quad*2;
        float b0 = __ldg(&bo[c0+col]), b1 = __ldg(&bo[c0+col+1]);
        ys[col*132 + r0]         = acc[nb][0] + b0;
        ys[(col+1)*132 + r0]     = acc[nb][1] + b1;
        ys[col*132 + r0 + 8]     = acc[nb][2] + b0;
        ys[(col+1)*132 + r0 + 8] = acc[nb][3] + b1;
    }
    __syncthreads();

    {
        int c = tid >> 1, hn = (tid & 1) * 64;
        float s = 0.f, s2 = 0.f;
        #pragma unroll 8
        for (int j = 0; j < 64; j++) {
            float v = ys[c*132 + hn + j];
            s += v; s2 += v*v;
        }
        s  += __shfl_xor_sync(0xffffffffu, s, 1);
        s2 += __shfl_xor_sync(0xffffffffu, s2, 1);
        if (!(tid & 1)) {
            int j = b*32 + blockIdx.x;
            d_ps1[(size_t)j*CC + c0 + c] = s;
            d_ps2[(size_t)j*CC + c0 + c] = s2;
        }
    }

    #pragma unroll
    for (int i = 0; i < 16; i++) {
        int f = tid + i*256;
        int row = f >> 5, q4 = f & 31;
        *(float4*)&d_Y[(size_t)(b*CC + c0 + row)*NN + n0 + q4*4] =
            *(float4*)&ys[row*132 + q4*4];
    }
}

// ======================= Kernel D: BN stats from partials ===================
__global__ __launch_bounds__(256) void bnstat_kernel(
    const float* __restrict__ gamma, const float* __restrict__ beta)
{
    const int c = threadIdx.x;
    float s = 0.f, s2 = 0.f;
    #pragma unroll 8
    for (int j = 0; j < 128; j++) {
        s  += d_ps1[(size_t)j*CC + c];
        s2 += d_ps2[(size_t)j*CC + c];
    }
    float mean = s  * (1.f/16384.f);
    float var  = s2 * (1.f/16384.f) - mean*mean;
    float sc = gamma[c] * rsqrtf(var + EPSc);
    d_scale[c] = sc;
    d_shift[c] = beta[c] - mean*sc;
}

// ======================= Kernel E: BN affine + ReLU + residual ==============
__global__ __launch_bounds__(256) void epilogue_kernel(
    const float* __restrict__ x, float* __restrict__ out)
{
    int i4 = blockIdx.x*256 + threadIdx.x;
    int idx = i4 * 4;
    int c = (idx >> 12) & 255;
    float sc = d_scale[c], sh = d_shift[c];
    float4 y   = *(const float4*)&d_Y[idx];
    float4 xin = ((const float4*)x)[i4];
    float4 r;
    r.x = fmaxf(fmaf(y.x, sc, sh), 0.f) + xin.x;
    r.y = fmaxf(fmaf(y.y, sc, sh), 0.f) + xin.y;
    r.z = fmaxf(fmaf(y.z, sc, sh), 0.f) + xin.z;
    r.w = fmaxf(fmaf(y.w, sc, sh), 0.f) + xin.w;
    ((float4*)out)[i4] = r;
}

// ============================ launch =======================================
extern "C" void kernel_launch(void* const* d_in, const int* in_sizes, int n_in,
                              void* d_out, int out_size)
{
    const float* x     = (const float*)d_in[0];
    const float* Wq    = (const float*)d_in[1];
    const float* bq    = (const float*)d_in[2];
    const float* Wk    = (const float*)d_in[3];
    const float* bk    = (const float*)d_in[4];
    const float* Wv    = (const float*)d_in[5];
    const float* bv    = (const float*)d_in[6];
    const float* Wo    = (const float*)d_in[7];
    const float* bo    = (const float*)d_in[8];
    const float* gamma = (const float*)d_in[9];
    const float* beta  = (const float*)d_in[10];
    float* out = (float*)d_out;

    cudaFuncSetAttribute(attn_kernel,
                         cudaFuncAttributeMaxDynamicSharedMemorySize, ATTN_SMEM_BYTES);
    cudaFuncSetAttribute(qkv_kernel,
                         cudaFuncAttributeMaxDynamicSharedMemorySize, QKV_SMEM);
    cudaFuncSetAttribute(oproj_kernel,
                         cudaFuncAttributeMaxDynamicSharedMemorySize, OPROJ_SMEM);

    wsplit_kernel<<<dim3(8, 4), 256>>>(Wq, Wk, Wv, Wo);
    qkv_kernel<<<dim3(NN/128, BB), 256, QKV_SMEM>>>(x, bq, bk, bv);
    attn_kernel<<<dim3(NN/128, BB), 256, ATTN_SMEM_BYTES>>>();
    oproj_kernel<<<dim3(NN/128, CC/128, BB), 256, OPROJ_SMEM>>>(bo);
    bnstat_kernel<<<1, 256>>>(gamma, beta);
    epilogue_kernel<<<(BB*CC*NN)/4/256, 256>>>(x, out);
}